// round 6
// baseline (speedup 1.0000x reference)
#include <cuda_runtime.h>
#include <cuda_bf16.h>
#include <cstdint>

// ---------------- problem constants ----------------
#define IN_CH   256
#define BATCH   8
#define KF      2304            // 9*256
#define NOUT    512
#define L2D     1024
#define MROWS   (BATCH * L2D)   // 8192
#define NCHK    (KF / 32)       // 72 k-chunks of 32

// GEMM tiling: CTA 128(M) x 256(N), 8 warps (2m x 4n) of 64x64
#define BK   32                 // k per chunk (2 bf16 k16-atoms)
#define NS   4                  // cp.async pipeline stages
#define TSZA (128 * 128)        // 16KB (128 rows x 128B [hi64|lo64])
#define TSZB (256 * 128)        // 32KB
#define STAGE (TSZA + TSZB)     // 48KB
#define SMEM_TOTAL (NS * STAGE) // 192KB

// scratch (__device__ globals: allocation-free rule)
// Split-bf16 chunked layout: for A-row r (flat im2col row), k-chunk c (32 k):
//   g_Ubf[(r*72 + c)*128 + 0..63]  = bf16 hi[32]
//   g_Ubf[(r*72 + c)*128 + 64..127]= bf16 lo[32]   (lo = x - (float)hi)
__device__ __align__(16) uint8_t g_Ubf[(size_t)MROWS * NCHK * 128];
__device__ __align__(16) uint8_t g_Bbf[(size_t)NOUT * NCHK * 128];

// ---------------- helpers ----------------
__device__ __forceinline__ void split_store(uint8_t* base, float v) {
    __nv_bfloat16 hi = __float2bfloat16(v);
    __nv_bfloat16 lo = __float2bfloat16(v - __bfloat162float(hi));
    *(__nv_bfloat16*)base = hi;
    *(__nv_bfloat16*)(base + 64) = lo;
}
__device__ __forceinline__ void cpa16(uint32_t dst, const void* src) {
    asm volatile("cp.async.cg.shared.global [%0], [%1], 16;" :: "r"(dst), "l"(src));
}
#define CP_COMMIT() asm volatile("cp.async.commit_group;" ::: "memory")
#define CP_WAITN()  asm volatile("cp.async.wait_group %0;" :: "n"(NS - 2) : "memory")

// swizzled smem tile: addr(row, kidx[4B units]) — identical to fp32 version.
__device__ __forceinline__ uint32_t lds32(const char* base, int row, int k) {
    return *(const uint32_t*)(base + row * 128 + (((k >> 2) ^ (row & 7)) << 4) + ((k & 3) << 2));
}
__device__ __forceinline__ void mma16(float* c, const uint32_t* a, const uint32_t* b) {
    asm volatile(
        "mma.sync.aligned.m16n8k16.row.col.f32.bf16.bf16.f32 "
        "{%0,%1,%2,%3}, {%4,%5,%6,%7}, {%8,%9}, {%0,%1,%2,%3};"
        : "+f"(c[0]), "+f"(c[1]), "+f"(c[2]), "+f"(c[3])
        : "r"(a[0]), "r"(a[1]), "r"(a[2]), "r"(a[3]), "r"(b[0]), "r"(b[1]));
}

// ---------------------------------------------------------------------------
// Kernel 1: im2col -> split-bf16 chunked layout. grid (9, 256, 8).
// Flat A index i = (b*KF + f)*1024 + l; row r = i/KF, k = i%KF.
// ---------------------------------------------------------------------------
__global__ void im2col_kernel(const float* __restrict__ x) {
    const int dd = blockIdx.x, ci = blockIdx.y, b = blockIdx.z;
    const int oy = dd / 3 - 1, ox = dd % 3 - 1;          // uniform per block
    const float* xp = x + (((size_t)(b * IN_CH + ci)) << 10);
    const uint32_t ibase = ((uint32_t)(b * KF + ci * 9 + dd)) << 10;
    #pragma unroll
    for (int s = 0; s < 4; s++) {
        int l = threadIdx.x + s * 256;
        int h = l >> 5, w = l & 31;
        int y = h + oy, xw = w + ox;
        float v = 0.0f;
        if ((unsigned)y < 32u && (unsigned)xw < 32u) v = xp[(y << 5) + xw];
        uint32_t i = ibase + l;
        uint32_t r = i / KF, k = i % KF;
        split_store(&g_Ubf[(((size_t)r * NCHK + (k >> 5)) << 7) + ((k & 31) << 1)], v);
    }
}

// ---------------------------------------------------------------------------
// Kernel 2: B^T expansion -> split-bf16 chunked. BT[co][k] = w[p][q][(j-m)&63]
// ---------------------------------------------------------------------------
__global__ void beffT_kernel(const float* __restrict__ wgt) {
    const int co = blockIdx.y;
    const int k = blockIdx.x * 256 + threadIdx.x;
    const int q = k >> 6, m = k & 63;
    const int p = co >> 6, j = co & 63;
    float v = wgt[((p * 36 + q) << 6) + ((j - m) & 63)];
    split_store(&g_Bbf[(((size_t)co * NCHK + (k >> 5)) << 7) + ((k & 31) << 1)], v);
}

// ---------------------------------------------------------------------------
// Kernel 3: split-bf16 mma.sync GEMM C[8192,512] = A @ B, fused transpose store.
// CTA 128x256, 8 warps (2m x 4n) of 64x64, 4-stage cp.async.
// Per k16 atom: 3 passes (Ah*Bh + Ah*Bl + Al*Bh), fp32 accumulate.
// ---------------------------------------------------------------------------
__global__ void __launch_bounds__(256, 1) gemm_kernel(float* __restrict__ out) {
    extern __shared__ char sm[];
    const int tid = threadIdx.x;
    const int lane = tid & 31;
    const int wid = tid >> 5;
    const int g = lane >> 2, t = lane & 3;
    const int wm = wid >> 2, wn = wid & 3;       // 2m x 4n
    const int bm = blockIdx.y * 128;
    const int bn = blockIdx.x * 256;

    float acc[4][8][4];
    #pragma unroll
    for (int i = 0; i < 4; i++)
        #pragma unroll
        for (int j = 0; j < 8; j++)
            #pragma unroll
            for (int q = 0; q < 4; q++) acc[i][j][q] = 0.0f;

    auto load_chunk = [&](int c, int s) {
        char* As = sm + s * STAGE;
        char* Bs = As + TSZA;
        #pragma unroll
        for (int i = 0; i < 4; i++) {            // A: 128 rows x 8 x 16B
            int id = tid + i * 256;
            int row = id >> 3, cj = id & 7;
            uint32_t swo = (uint32_t)(row * 128 + ((cj ^ (row & 7)) << 4));
            cpa16((uint32_t)__cvta_generic_to_shared(As + swo),
                  &g_Ubf[(((size_t)(bm + row) * NCHK + c) << 7) + (cj << 4)]);
        }
        #pragma unroll
        for (int i = 0; i < 8; i++) {            // B: 256 rows x 8 x 16B
            int id = tid + i * 256;
            int row = id >> 3, cj = id & 7;
            uint32_t swo = (uint32_t)(row * 128 + ((cj ^ (row & 7)) << 4));
            cpa16((uint32_t)__cvta_generic_to_shared(Bs + swo),
                  &g_Bbf[(((size_t)(bn + row) * NCHK + c) << 7) + (cj << 4)]);
        }
    };

    auto compute = [&](int s) {
        const char* As = sm + s * STAGE;
        const char* Bs = As + TSZA;
        #pragma unroll
        for (int ka = 0; ka < 2; ka++) {
            const int kh = ka * 8;               // hi kidx base (4B units)
            const int kl = kh + 16;              // lo kidx base
            uint32_t ah[4][4], al[4][4], bh[8][2], bl[8][2];
            #pragma unroll
            for (int ma = 0; ma < 4; ma++) {
                int r0 = wm * 64 + ma * 16 + g;
                ah[ma][0] = lds32(As, r0,     kh + t);
                ah[ma][1] = lds32(As, r0 + 8, kh + t);
                ah[ma][2] = lds32(As, r0,     kh + t + 4);
                ah[ma][3] = lds32(As, r0 + 8, kh + t + 4);
                al[ma][0] = lds32(As, r0,     kl + t);
                al[ma][1] = lds32(As, r0 + 8, kl + t);
                al[ma][2] = lds32(As, r0,     kl + t + 4);
                al[ma][3] = lds32(As, r0 + 8, kl + t + 4);
            }
            #pragma unroll
            for (int na = 0; na < 8; na++) {
                int n0 = wn * 64 + na * 8 + g;
                bh[na][0] = lds32(Bs, n0, kh + t);
                bh[na][1] = lds32(Bs, n0, kh + t + 4);
                bl[na][0] = lds32(Bs, n0, kl + t);
                bl[na][1] = lds32(Bs, n0, kl + t + 4);
            }
            #pragma unroll
            for (int ma = 0; ma < 4; ma++)
                #pragma unroll
                for (int na = 0; na < 8; na++) {
                    mma16(acc[ma][na], ah[ma], bh[na]);
                    mma16(acc[ma][na], ah[ma], bl[na]);
                    mma16(acc[ma][na], al[ma], bh[na]);
                }
        }
    };

    // prologue: prefetch NS-1 chunks
    #pragma unroll
    for (int s = 0; s < NS - 1; s++) { load_chunk(s, s); CP_COMMIT(); }

    for (int c = 0; c < NCHK; c++) {
        CP_WAITN();
        __syncthreads();
        const int cn = c + NS - 1;
        if (cn < NCHK) { load_chunk(cn, cn % NS); CP_COMMIT(); }
        compute(c % NS);
    }

    // epilogue: C[r][co] -> out[b][co][l2], r = b*1024 + l2
    #pragma unroll
    for (int ma = 0; ma < 4; ma++) {
        #pragma unroll
        for (int half = 0; half < 2; half++) {
            const int r = bm + wm * 64 + ma * 16 + g + half * 8;
            const int b = r >> 10;
            const int l2 = r & (L2D - 1);
            float* op = out + (((size_t)b * NOUT) << 10) + l2;
            #pragma unroll
            for (int na = 0; na < 8; na++) {
                const int co = bn + wn * 64 + na * 8 + t * 2;
                op[(size_t)co << 10]       = acc[ma][na][half * 2 + 0];
                op[(size_t)(co + 1) << 10] = acc[ma][na][half * 2 + 1];
            }
        }
    }
}

// ---------------------------------------------------------------------------
extern "C" void kernel_launch(void* const* d_in, const int* in_sizes, int n_in,
                              void* d_out, int out_size) {
    const float* x = (const float*)d_in[0];
    const float* w = (const float*)d_in[1];
    if (n_in >= 2 && in_sizes[0] == 8 * 36 * 64) {   // defensive swap by size
        const float* tp = x; x = w; w = tp;
    }
    float* out = (float*)d_out;

    cudaFuncSetAttribute(gemm_kernel, cudaFuncAttributeMaxDynamicSharedMemorySize, SMEM_TOTAL);

    im2col_kernel<<<dim3(9, IN_CH, BATCH), 256>>>(x);
    beffT_kernel<<<dim3(KF / 256, NOUT), 256>>>(w);
    gemm_kernel<<<dim3(NOUT / 256, MROWS / 128), 256, SMEM_TOTAL>>>(out);
    (void)out_size;
}